// round 6
// baseline (speedup 1.0000x reference)
#include <cuda_runtime.h>
#include <math.h>
#include <stdint.h>

#define T_TOK 2048
#define D_DIM 1024
#define F_DIM 4096
#define E_NUM 8
#define NPAIR (T_TOK * 2)

#define BM 128
#define BK 32
#define SA_STR 36      // A smem row stride (floats)
#define SB_STR 136     // B smem row stride (floats)
#define A_BYTES (BM * SA_STR * 4)       // 18432
#define B_BYTES (BK * SB_STR * 4)       // 17408
#define STAGE_BYTES (A_BYTES + B_BYTES) // 35840
#define NSTAGE 3
#define SMEM_TOTAL (NSTAGE * STAGE_BYTES)  // 107520 -> 2 CTAs/SM

// ---------------- scratch (device globals) ----------------
__device__ int   g_off[E_NUM + 1];
__device__ int   g_pair_tok[NPAIR];
__device__ int   g_pair_slot[NPAIR];
__device__ float g_pair_w[NPAIR];
__device__ int   g_tok_e[NPAIR];
__device__ float g_tok_w[NPAIR];
__device__ float g_h[(size_t)NPAIR * F_DIM];     // 64 MB
__device__ float g_y[(size_t)NPAIR * D_DIM];     // 16 MB

// ---------------- PTX helpers (sm_103 baseline; no 'a'-gated features) ----------------
__device__ __forceinline__ uint32_t smem_u32(const void* p) {
    uint32_t a;
    asm("{ .reg .u64 t; cvta.to.shared.u64 t, %1; cvt.u32.u64 %0, t; }" : "=r"(a) : "l"(p));
    return a;
}
__device__ __forceinline__ void cp16(uint32_t dst, const void* src) {
    asm volatile("cp.async.cg.shared.global [%0], [%1], 16;" :: "r"(dst), "l"(src));
}
#define CP_COMMIT() asm volatile("cp.async.commit_group;" ::: "memory")
#define CP_WAIT(n)  asm volatile("cp.async.wait_group %0;" :: "n"(n) : "memory")

__device__ __forceinline__ uint32_t lds32(uint32_t addr) {
    uint32_t v;
    asm volatile("ld.shared.b32 %0, [%1];" : "=r"(v) : "r"(addr));
    return v;
}
// in-place fp32 -> tf32 (round-to-nearest) of 4 consecutive floats in smem
__device__ __forceinline__ void cvt4_inplace(uint32_t a) {
    float x0, x1, x2, x3;
    asm volatile("ld.shared.v4.f32 {%0,%1,%2,%3}, [%4];"
        : "=f"(x0), "=f"(x1), "=f"(x2), "=f"(x3) : "r"(a));
    uint32_t c0, c1, c2, c3;
    asm("cvt.rna.tf32.f32 %0, %1;" : "=r"(c0) : "f"(x0));
    asm("cvt.rna.tf32.f32 %0, %1;" : "=r"(c1) : "f"(x1));
    asm("cvt.rna.tf32.f32 %0, %1;" : "=r"(c2) : "f"(x2));
    asm("cvt.rna.tf32.f32 %0, %1;" : "=r"(c3) : "f"(x3));
    asm volatile("st.shared.v4.b32 [%0], {%1,%2,%3,%4};"
        :: "r"(a), "r"(c0), "r"(c1), "r"(c2), "r"(c3) : "memory");
}
__device__ __forceinline__ void ldm4(uint32_t addr, uint32_t* r) {
    asm volatile("ldmatrix.sync.aligned.m8n8.x4.shared.b16 {%0,%1,%2,%3}, [%4];"
        : "=r"(r[0]), "=r"(r[1]), "=r"(r[2]), "=r"(r[3]) : "r"(addr));
}
__device__ __forceinline__ void mma8(float* d, uint32_t a0, uint32_t a1, uint32_t a2, uint32_t a3,
                                     uint32_t b0, uint32_t b1) {
    asm volatile(
        "mma.sync.aligned.m16n8k8.row.col.f32.tf32.tf32.f32 "
        "{%0,%1,%2,%3}, {%4,%5,%6,%7}, {%8,%9}, {%0,%1,%2,%3};"
        : "+f"(d[0]), "+f"(d[1]), "+f"(d[2]), "+f"(d[3])
        : "r"(a0), "r"(a1), "r"(a2), "r"(a3), "r"(b0), "r"(b1));
}

// ---------------- 1) router (exact fp32) ----------------
__global__ void router_kernel(const float* __restrict__ x, const float* __restrict__ wr) {
    int warp = threadIdx.x >> 5;
    int lane = threadIdx.x & 31;
    int t = blockIdx.x * 8 + warp;
    if (t >= T_TOK) return;

    float acc[E_NUM];
#pragma unroll
    for (int e = 0; e < E_NUM; e++) acc[e] = 0.f;

    const float* xr = x + (size_t)t * D_DIM;
    for (int d = lane; d < D_DIM; d += 32) {
        float xv = xr[d];
        const float4* w4 = (const float4*)(wr + (size_t)d * E_NUM);
        float4 w0 = w4[0];
        float4 w1 = w4[1];
        acc[0] += xv * w0.x; acc[1] += xv * w0.y;
        acc[2] += xv * w0.z; acc[3] += xv * w0.w;
        acc[4] += xv * w1.x; acc[5] += xv * w1.y;
        acc[6] += xv * w1.z; acc[7] += xv * w1.w;
    }
#pragma unroll
    for (int off = 16; off > 0; off >>= 1)
#pragma unroll
        for (int e = 0; e < E_NUM; e++)
            acc[e] += __shfl_xor_sync(0xFFFFFFFFu, acc[e], off);
    if (lane == 0) {
        int i1 = 0;
#pragma unroll
        for (int e = 1; e < E_NUM; e++) if (acc[e] > acc[i1]) i1 = e;
        int i2 = (i1 == 0) ? 1 : 0;
#pragma unroll
        for (int e = 0; e < E_NUM; e++)
            if (e != i1 && acc[e] > acc[i2]) i2 = e;
        float w1 = 1.f / (1.f + expf(acc[i2] - acc[i1]));
        g_tok_e[t * 2 + 0] = i1;
        g_tok_e[t * 2 + 1] = i2;
        g_tok_w[t * 2 + 0] = w1;
        g_tok_w[t * 2 + 1] = 1.f - w1;
    }
}

// ---------------- 2) per-expert lists ----------------
__global__ void assign_kernel() {
    __shared__ int s_cnt[E_NUM];
    __shared__ int s_fill[E_NUM];
    if (threadIdx.x < E_NUM) s_cnt[threadIdx.x] = 0;
    __syncthreads();
    for (int p = threadIdx.x; p < NPAIR; p += blockDim.x)
        atomicAdd(&s_cnt[g_tok_e[p]], 1);
    __syncthreads();
    if (threadIdx.x == 0) {
        int o = 0;
        for (int e = 0; e < E_NUM; e++) { g_off[e] = o; s_fill[e] = o; o += s_cnt[e]; }
        g_off[E_NUM] = o;
    }
    __syncthreads();
    for (int p = threadIdx.x; p < NPAIR; p += blockDim.x) {
        int e = g_tok_e[p];
        int pos = atomicAdd(&s_fill[e], 1);
        g_pair_tok[pos]  = p >> 1;
        g_pair_slot[pos] = p & 1;
        g_pair_w[pos]    = g_tok_w[p];
    }
}

// ---------------- in-place tf32 convert pass (mirrors the cp.async fill mapping) ----------------
__device__ __forceinline__ void cvt_pass(uint32_t sA, uint32_t sB, int tid) {
    int aj = tid & 7;
    int col4 = tid & 31;
    int kr0 = tid >> 5;
#pragma unroll
    for (int i = 0; i < 4; i++)
        cvt4_inplace(sA + (uint32_t)((((tid >> 3) + i * 32) * SA_STR) * 4 + aj * 16));
#pragma unroll
    for (int i = 0; i < 4; i++)
        cvt4_inplace(sB + (uint32_t)(((kr0 + i * 8) * SB_STR) * 4 + col4 * 16));
}

// ---------------- GEMM compute core: ldmatrix A + scalar B, data already tf32 ----------------
__device__ __forceinline__ void gemm_compute(uint32_t sA, uint32_t sB,
                                             int wm, int wn, int lane,
                                             float acc[4][4][4]) {
    int g = lane >> 2, t = lane & 3;
    // ldmatrix lane address: matrix mi = lane>>3 covers (rowoff = (mi&1)*8, coloff = (mi>>1)*4)
    int r8 = lane & 7, mi = lane >> 3;
    uint32_t laneA = sA + (uint32_t)(((wm + ((mi & 1) << 3) + r8) * SA_STR + ((mi >> 1) << 2)) * 4);
    uint32_t bBase = sB + (uint32_t)((t * SB_STR + wn + g) * 4);
#pragma unroll
    for (int ks = 0; ks < 4; ks++) {
        uint32_t Af[4][4];
#pragma unroll
        for (int mf = 0; mf < 4; mf++)
            ldm4(laneA + (uint32_t)(mf * 16 * SA_STR * 4 + ks * 32), Af[mf]);
        uint32_t bK = bBase + (uint32_t)(ks * 8 * SB_STR * 4);
        uint32_t B0[4], B1[4];
#pragma unroll
        for (int nf = 0; nf < 4; nf++) {
            uint32_t bb = bK + nf * 32;
            B0[nf] = lds32(bb);
            B1[nf] = lds32(bb + 4 * SB_STR * 4);
        }
#pragma unroll
        for (int mf = 0; mf < 4; mf++)
#pragma unroll
            for (int nf = 0; nf < 4; nf++)
                mma8(acc[mf][nf], Af[mf][0], Af[mf][1], Af[mf][2], Af[mf][3], B0[nf], B1[nf]);
    }
}

// ---------------- 3) fused gate+up GEMM + SiLU -> g_h ----------------
// CTA computes 128 pairs x 64 F-cols of BOTH gate and up.
// B tile: cols [0,64) = Wg, cols [64,128) = Wu. Warps wn<64 -> gate, wn>=64 -> up.
__global__ void __launch_bounds__(256, 2)
gemm_gu(const float* __restrict__ x,
        const float* __restrict__ Wg,
        const float* __restrict__ Wu) {
    int e = blockIdx.z;
    int base = g_off[e] + blockIdx.x * BM;
    int end  = g_off[e + 1];
    if (base >= end) return;
    int nb = blockIdx.y * 64;
    const float* wgp = Wg + (size_t)e * D_DIM * F_DIM;
    const float* wup = Wu + (size_t)e * D_DIM * F_DIM;

    extern __shared__ char smem[];
    uint32_t s0 = smem_u32(smem);

    int tid = threadIdx.x, lane = tid & 31, wid = tid >> 5;
    int g = lane >> 2, t = lane & 3;
    int wm = (wid & 1) * 64, wn = (wid >> 1) * 32;   // wn in {0,32,64,96}

    const float* aSrc[4];
#pragma unroll
    for (int i = 0; i < 4; i++) {
        int p = base + (tid >> 3) + i * 32;
        if (p > end - 1) p = end - 1;
        aSrc[i] = x + (size_t)g_pair_tok[p] * D_DIM;
    }
    int aj = tid & 7;
    int col4 = tid & 31;
    const float* bW = (col4 < 16) ? (wgp + nb + col4 * 4) : (wup + nb + (col4 - 16) * 4);
    int kr0 = tid >> 5;

    float acc[4][4][4];
#pragma unroll
    for (int mf = 0; mf < 4; mf++)
#pragma unroll
        for (int nf = 0; nf < 4; nf++)
#pragma unroll
            for (int c = 0; c < 4; c++) acc[mf][nf][c] = 0.f;

    const int NC = D_DIM / BK;  // 32

#pragma unroll
    for (int s = 0; s < 2; s++) {
        uint32_t sA = s0 + s * STAGE_BYTES, sB = sA + A_BYTES;
        int kb = s * BK;
#pragma unroll
        for (int i = 0; i < 4; i++)
            cp16(sA + (uint32_t)(((tid >> 3) + i * 32) * SA_STR * 4 + aj * 16),
                 aSrc[i] + kb + aj * 4);
#pragma unroll
        for (int i = 0; i < 4; i++) {
            int kr = kr0 + i * 8;
            cp16(sB + (uint32_t)(kr * SB_STR * 4 + col4 * 16),
                 bW + (size_t)(kb + kr) * F_DIM);
        }
        CP_COMMIT();
    }

    for (int c = 0; c < NC; c++) {
        if (c + 2 < NC) {
            CP_WAIT(1);           // group c complete
            __syncthreads();      // all threads done computing c-1; slot (c+2)%3 free
            int kb = (c + 2) * BK;
            uint32_t sA = s0 + ((c + 2) % NSTAGE) * STAGE_BYTES;
            uint32_t sB = sA + A_BYTES;
#pragma unroll
            for (int i = 0; i < 4; i++)
                cp16(sA + (uint32_t)(((tid >> 3) + i * 32) * SA_STR * 4 + aj * 16),
                     aSrc[i] + kb + aj * 4);
#pragma unroll
            for (int i = 0; i < 4; i++) {
                int kr = kr0 + i * 8;
                cp16(sB + (uint32_t)(kr * SB_STR * 4 + col4 * 16),
                     bW + (size_t)(kb + kr) * F_DIM);
            }
            CP_COMMIT();
        } else {
            CP_WAIT(0);
            __syncthreads();
        }
        uint32_t sA = s0 + (c % NSTAGE) * STAGE_BYTES;
        cvt_pass(sA, sA + A_BYTES, tid);
        __syncthreads();
        gemm_compute(sA, sA + A_BYTES, wm, wn, lane, acc);
    }

    // ----- fused SiLU epilogue via smem staging of the up tile -----
    __syncthreads();   // all compute done; stage 0 region reusable
    float* s_up = (float*)smem;        // [128][68] floats = 34816 B <= STAGE_BYTES
    if (wn >= 64) {
#pragma unroll
        for (int mf = 0; mf < 4; mf++) {
            int r0 = wm + mf * 16 + g;
#pragma unroll
            for (int nf = 0; nf < 4; nf++) {
                int col = (wn - 64) + nf * 8 + 2 * t;
                *(float2*)&s_up[r0 * 68 + col]       = make_float2(acc[mf][nf][0], acc[mf][nf][1]);
                *(float2*)&s_up[(r0 + 8) * 68 + col] = make_float2(acc[mf][nf][2], acc[mf][nf][3]);
            }
        }
    }
    __syncthreads();
    if (wn < 64) {
#pragma unroll
        for (int mf = 0; mf < 4; mf++) {
            int r0 = wm + mf * 16 + g;
            int p0 = base + r0;
            int p1 = p0 + 8;
#pragma unroll
            for (int nf = 0; nf < 4; nf++) {
                int col = wn + nf * 8 + 2 * t;
                float2 u0 = *(float2*)&s_up[r0 * 68 + col];
                float2 u1 = *(float2*)&s_up[(r0 + 8) * 68 + col];
                if (p0 < end) {
                    float g0 = acc[mf][nf][0], g1 = acc[mf][nf][1];
                    *(float2*)(g_h + (size_t)p0 * F_DIM + nb + col) =
                        make_float2(g0 / (1.f + expf(-g0)) * u0.x,
                                    g1 / (1.f + expf(-g1)) * u0.y);
                }
                if (p1 < end) {
                    float g2 = acc[mf][nf][2], g3 = acc[mf][nf][3];
                    *(float2*)(g_h + (size_t)p1 * F_DIM + nb + col) =
                        make_float2(g2 / (1.f + expf(-g2)) * u1.x,
                                    g3 / (1.f + expf(-g3)) * u1.y);
                }
            }
        }
    }
}

// ---------------- 4) down GEMM: g_y[tok*2+slot] = w * (g_h row @ Wd[e]) ----------------
__global__ void __launch_bounds__(256, 2)
gemm_down(const float* __restrict__ Wd) {
    int e = blockIdx.z;
    int base = g_off[e] + blockIdx.x * BM;
    int end  = g_off[e + 1];
    if (base >= end) return;
    int nb = blockIdx.y * 128;
    const float* W = Wd + (size_t)e * F_DIM * D_DIM;

    extern __shared__ char smem[];
    uint32_t s0 = smem_u32(smem);

    int tid = threadIdx.x, lane = tid & 31, wid = tid >> 5;
    int g = lane >> 2, t = lane & 3;
    int wm = (wid & 1) * 64, wn = (wid >> 1) * 32;

    const float* aSrc[4];
#pragma unroll
    for (int i = 0; i < 4; i++) {
        int p = base + (tid >> 3) + i * 32;
        if (p > end - 1) p = end - 1;
        aSrc[i] = g_h + (size_t)p * F_DIM;
    }
    int aj = tid & 7;
    int col4 = tid & 31;
    int kr0 = tid >> 5;

    float acc[4][4][4];
#pragma unroll
    for (int mf = 0; mf < 4; mf++)
#pragma unroll
        for (int nf = 0; nf < 4; nf++)
#pragma unroll
            for (int c = 0; c < 4; c++) acc[mf][nf][c] = 0.f;

    const int NC = F_DIM / BK;  // 128

#pragma unroll
    for (int s = 0; s < 2; s++) {
        uint32_t sA = s0 + s * STAGE_BYTES, sB = sA + A_BYTES;
        int kb = s * BK;
#pragma unroll
        for (int i = 0; i < 4; i++)
            cp16(sA + (uint32_t)(((tid >> 3) + i * 32) * SA_STR * 4 + aj * 16),
                 aSrc[i] + kb + aj * 4);
#pragma unroll
        for (int i = 0; i < 4; i++) {
            int kr = kr0 + i * 8;
            cp16(sB + (uint32_t)(kr * SB_STR * 4 + col4 * 16),
                 W + (size_t)(kb + kr) * D_DIM + nb + col4 * 4);
        }
        CP_COMMIT();
    }

    for (int c = 0; c < NC; c++) {
        if (c + 2 < NC) {
            CP_WAIT(1);
            __syncthreads();
            int kb = (c + 2) * BK;
            uint32_t sA = s0 + ((c + 2) % NSTAGE) * STAGE_BYTES;
            uint32_t sB = sA + A_BYTES;
#pragma unroll
            for (int i = 0; i < 4; i++)
                cp16(sA + (uint32_t)(((tid >> 3) + i * 32) * SA_STR * 4 + aj * 16),
                     aSrc[i] + kb + aj * 4);
#pragma unroll
            for (int i = 0; i < 4; i++) {
                int kr = kr0 + i * 8;
                cp16(sB + (uint32_t)(kr * SB_STR * 4 + col4 * 16),
                     W + (size_t)(kb + kr) * D_DIM + nb + col4 * 4);
            }
            CP_COMMIT();
        } else {
            CP_WAIT(0);
            __syncthreads();
        }
        uint32_t sA = s0 + (c % NSTAGE) * STAGE_BYTES;
        cvt_pass(sA, sA + A_BYTES, tid);
        __syncthreads();
        gemm_compute(sA, sA + A_BYTES, wm, wn, lane, acc);
    }

#pragma unroll
    for (int mf = 0; mf < 4; mf++) {
        int p0 = base + wm + mf * 16 + g;
        int p1 = p0 + 8;
#pragma unroll
        for (int nf = 0; nf < 4; nf++) {
            int col = nb + wn + nf * 8 + 2 * t;
            if (p0 < end) {
                float w = g_pair_w[p0];
                size_t row = (size_t)(g_pair_tok[p0] * 2 + g_pair_slot[p0]);
                *(float2*)(g_y + row * D_DIM + col) =
                    make_float2(w * acc[mf][nf][0], w * acc[mf][nf][1]);
            }
            if (p1 < end) {
                float w = g_pair_w[p1];
                size_t row = (size_t)(g_pair_tok[p1] * 2 + g_pair_slot[p1]);
                *(float2*)(g_y + row * D_DIM + col) =
                    make_float2(w * acc[mf][nf][2], w * acc[mf][nf][3]);
            }
        }
    }
}

// ---------------- 5) combine ----------------
__global__ void combine_kernel(float* __restrict__ out) {
    int i = blockIdx.x * blockDim.x + threadIdx.x;
    if (i >= T_TOK * D_DIM) return;
    int t = i >> 10;
    int d = i & (D_DIM - 1);
    out[i] = g_y[((size_t)(t * 2)) * D_DIM + d] + g_y[((size_t)(t * 2 + 1)) * D_DIM + d];
}

// ---------------- launch ----------------
extern "C" void kernel_launch(void* const* d_in, const int* in_sizes, int n_in,
                              void* d_out, int out_size) {
    const float* x  = (const float*)d_in[0];
    const float* wr = (const float*)d_in[1];
    const float* Wg = (const float*)d_in[2];
    const float* Wu = (const float*)d_in[3];
    const float* Wd = (const float*)d_in[4];
    float* out = (float*)d_out;

    cudaFuncSetAttribute(gemm_gu,   cudaFuncAttributeMaxDynamicSharedMemorySize, SMEM_TOTAL);
    cudaFuncSetAttribute(gemm_down, cudaFuncAttributeMaxDynamicSharedMemorySize, SMEM_TOTAL);

    router_kernel<<<T_TOK / 8, 256>>>(x, wr);
    assign_kernel<<<1, 256>>>();
    gemm_gu<<<dim3(NPAIR / BM, F_DIM / 64, E_NUM), 256, SMEM_TOTAL>>>(x, Wg, Wu);
    gemm_down<<<dim3(NPAIR / BM, D_DIM / 128, E_NUM), 256, SMEM_TOTAL>>>(Wd);
    combine_kernel<<<(T_TOK * D_DIM + 255) / 256, 256>>>(out);
}

// round 7
// speedup vs baseline: 1.7709x; 1.7709x over previous
#include <cuda_runtime.h>
#include <cuda_fp16.h>
#include <math.h>
#include <stdint.h>

#define T_TOK 2048
#define D_DIM 1024
#define F_DIM 4096
#define E_NUM 8
#define NPAIR (T_TOK * 2)

#define BM 128
#define BK 32
#define SAH 40     // A smem row stride (halfs) = 80B: ldmatrix-conflict-free
#define SBH 136    // B smem row stride (halfs) = 272B: ldmatrix/STS-conflict-free
#define A_TILE (BM * SAH * 2)     // 10240 B
#define B_TILE (BK * SBH * 2)     // 8704 B
#define SMEM_TOTAL (2 * A_TILE + 2 * B_TILE)  // 37888 B

// ---------------- scratch (device globals) ----------------
__device__ int    g_off[E_NUM + 1];
__device__ int    g_pair_tok[NPAIR];
__device__ int    g_pair_slot[NPAIR];
__device__ float  g_pair_w[NPAIR];
__device__ int    g_tok_e[NPAIR];
__device__ float  g_tok_w[NPAIR];
__device__ __half g_x16[(size_t)T_TOK * D_DIM];   // 4 MB
__device__ __half g_h16[(size_t)NPAIR * F_DIM];   // 32 MB
__device__ float  g_y[(size_t)NPAIR * D_DIM];     // 16 MB

// ---------------- PTX helpers (sm_103 baseline; no 'a'-gated features) ----------------
__device__ __forceinline__ uint32_t smem_u32(const void* p) {
    uint32_t a;
    asm("{ .reg .u64 t; cvta.to.shared.u64 t, %1; cvt.u32.u64 %0, t; }" : "=r"(a) : "l"(p));
    return a;
}
__device__ __forceinline__ void cp16(uint32_t dst, const void* src) {
    asm volatile("cp.async.cg.shared.global [%0], [%1], 16;" :: "r"(dst), "l"(src));
}
#define CP_COMMIT() asm volatile("cp.async.commit_group;" ::: "memory")
#define CP_WAIT(n)  asm volatile("cp.async.wait_group %0;" :: "n"(n) : "memory")

__device__ __forceinline__ void ldm4(uint32_t a, uint32_t* r) {
    asm volatile("ldmatrix.sync.aligned.m8n8.x4.shared.b16 {%0,%1,%2,%3}, [%4];"
        : "=r"(r[0]), "=r"(r[1]), "=r"(r[2]), "=r"(r[3]) : "r"(a));
}
__device__ __forceinline__ void ldm2t(uint32_t a, uint32_t* r) {
    asm volatile("ldmatrix.sync.aligned.m8n8.x2.trans.shared.b16 {%0,%1}, [%2];"
        : "=r"(r[0]), "=r"(r[1]) : "r"(a));
}
__device__ __forceinline__ void mma16(float* d, const uint32_t* a, const uint32_t* b) {
    asm volatile(
        "mma.sync.aligned.m16n8k16.row.col.f32.f16.f16.f32 "
        "{%0,%1,%2,%3}, {%4,%5,%6,%7}, {%8,%9}, {%0,%1,%2,%3};"
        : "+f"(d[0]), "+f"(d[1]), "+f"(d[2]), "+f"(d[3])
        : "r"(a[0]), "r"(a[1]), "r"(a[2]), "r"(a[3]), "r"(b[0]), "r"(b[1]));
}

// cvt fp32x4 -> fp16x4 and STS 8B
__device__ __forceinline__ void stsB4(uint32_t addr, float4 v) {
    __half2 h0 = __floats2half2_rn(v.x, v.y);
    __half2 h1 = __floats2half2_rn(v.z, v.w);
    asm volatile("st.shared.v2.b32 [%0], {%1,%2};"
        :: "r"(addr), "r"(*(uint32_t*)&h0), "r"(*(uint32_t*)&h1) : "memory");
}

// ---------------- 1) router (exact fp32) ----------------
__global__ void router_kernel(const float* __restrict__ x, const float* __restrict__ wr) {
    int warp = threadIdx.x >> 5;
    int lane = threadIdx.x & 31;
    int t = blockIdx.x * 8 + warp;
    if (t >= T_TOK) return;

    float acc[E_NUM];
#pragma unroll
    for (int e = 0; e < E_NUM; e++) acc[e] = 0.f;

    const float* xr = x + (size_t)t * D_DIM;
    for (int d = lane; d < D_DIM; d += 32) {
        float xv = xr[d];
        const float4* w4 = (const float4*)(wr + (size_t)d * E_NUM);
        float4 w0 = w4[0];
        float4 w1 = w4[1];
        acc[0] += xv * w0.x; acc[1] += xv * w0.y;
        acc[2] += xv * w0.z; acc[3] += xv * w0.w;
        acc[4] += xv * w1.x; acc[5] += xv * w1.y;
        acc[6] += xv * w1.z; acc[7] += xv * w1.w;
    }
#pragma unroll
    for (int off = 16; off > 0; off >>= 1)
#pragma unroll
        for (int e = 0; e < E_NUM; e++)
            acc[e] += __shfl_xor_sync(0xFFFFFFFFu, acc[e], off);
    if (lane == 0) {
        int i1 = 0;
#pragma unroll
        for (int e = 1; e < E_NUM; e++) if (acc[e] > acc[i1]) i1 = e;
        int i2 = (i1 == 0) ? 1 : 0;
#pragma unroll
        for (int e = 0; e < E_NUM; e++)
            if (e != i1 && acc[e] > acc[i2]) i2 = e;
        float w1 = 1.f / (1.f + expf(acc[i2] - acc[i1]));
        g_tok_e[t * 2 + 0] = i1;
        g_tok_e[t * 2 + 1] = i2;
        g_tok_w[t * 2 + 0] = w1;
        g_tok_w[t * 2 + 1] = 1.f - w1;
    }
}

// ---------------- 2) per-expert lists ----------------
__global__ void assign_kernel() {
    __shared__ int s_cnt[E_NUM];
    __shared__ int s_fill[E_NUM];
    if (threadIdx.x < E_NUM) s_cnt[threadIdx.x] = 0;
    __syncthreads();
    for (int p = threadIdx.x; p < NPAIR; p += blockDim.x)
        atomicAdd(&s_cnt[g_tok_e[p]], 1);
    __syncthreads();
    if (threadIdx.x == 0) {
        int o = 0;
        for (int e = 0; e < E_NUM; e++) { g_off[e] = o; s_fill[e] = o; o += s_cnt[e]; }
        g_off[E_NUM] = o;
    }
    __syncthreads();
    for (int p = threadIdx.x; p < NPAIR; p += blockDim.x) {
        int e = g_tok_e[p];
        int pos = atomicAdd(&s_fill[e], 1);
        g_pair_tok[pos]  = p >> 1;
        g_pair_slot[pos] = p & 1;
        g_pair_w[pos]    = g_tok_w[p];
    }
}

// ---------------- 2b) x -> fp16 scratch ----------------
__global__ void cvt_x_kernel(const float* __restrict__ x) {
    int i = blockIdx.x * 256 + threadIdx.x;   // float4 index; total T*D/4 = 524288
    float4 v = ((const float4*)x)[i];
    __half2 h0 = __floats2half2_rn(v.x, v.y);
    __half2 h1 = __floats2half2_rn(v.z, v.w);
    ((uint2*)g_x16)[i] = make_uint2(*(uint32_t*)&h0, *(uint32_t*)&h1);
}

// ---------------- fp16 GEMM compute core (ldmatrix + m16n8k16) ----------------
// warp tile 64(m) x 32(n); acc[mf][nf][4]
__device__ __forceinline__ void gemm_f16(uint32_t sA, uint32_t sB,
                                         int wm, int wn, int lane,
                                         float acc[4][4][4]) {
    int r8 = lane & 7, mi = lane >> 3;
    uint32_t aAddr = sA + (uint32_t)((wm + ((mi & 1) << 3) + r8) * (SAH * 2) + ((mi >> 1) << 4));
    uint32_t bAddr = sB + (uint32_t)((lane & 15) * (SBH * 2));
#pragma unroll
    for (int ks = 0; ks < 2; ks++) {
        uint32_t Af[4][4];
#pragma unroll
        for (int mf = 0; mf < 4; mf++)
            ldm4(aAddr + (uint32_t)(mf * 16 * SAH * 2 + ks * 32), Af[mf]);
        uint32_t Bf[4][2];
#pragma unroll
        for (int nf = 0; nf < 4; nf++)
            ldm2t(bAddr + (uint32_t)(ks * 16 * SBH * 2 + (wn + nf * 8) * 2), Bf[nf]);
#pragma unroll
        for (int mf = 0; mf < 4; mf++)
#pragma unroll
            for (int nf = 0; nf < 4; nf++)
                mma16(acc[mf][nf], Af[mf], Bf[nf]);
    }
}

// ---------------- 3) fused gate+up GEMM + SiLU -> g_h16 ----------------
// CTA: 128 pairs x 64 F-cols of BOTH gate and up. B tile cols [0,64)=Wg, [64,128)=Wu.
__global__ void __launch_bounds__(256, 2)
gemm_gu(const float* __restrict__ Wg, const float* __restrict__ Wu) {
    int e = blockIdx.z;
    int base = g_off[e] + blockIdx.x * BM;
    int end  = g_off[e + 1];
    if (base >= end) return;
    int nb = blockIdx.y * 64;
    const float* wgp = Wg + (size_t)e * D_DIM * F_DIM;
    const float* wup = Wu + (size_t)e * D_DIM * F_DIM;

    extern __shared__ char smem[];
    uint32_t s0 = smem_u32(smem);
    // layout: A0, A1, B0, B1
    uint32_t sA[2] = { s0, s0 + A_TILE };
    uint32_t sB[2] = { s0 + 2 * A_TILE, s0 + 2 * A_TILE + B_TILE };

    int tid = threadIdx.x, lane = tid & 31, wid = tid >> 5;
    int g = lane >> 2, t = lane & 3;
    int wm = (wid & 1) * 64, wn = (wid >> 1) * 32;   // wn in {0,32,64,96}

    // A gather: each thread fills 2x16B of row r = tid>>1
    int rA = tid >> 1;
    int cc0 = (tid & 1) * 2;
    int pA = base + rA; if (pA > end - 1) pA = end - 1;
    const __half* aRow = g_x16 + (size_t)g_pair_tok[pA] * D_DIM;

    // B fill: thread reads 4 floats at (kr, col4*4) over 4 k-row groups
    int col4 = tid & 31;
    int kr0 = tid >> 5;
    const float* bW = (col4 < 16) ? (wgp + nb + col4 * 4) : (wup + nb + (col4 - 16) * 4);

    float acc[4][4][4];
#pragma unroll
    for (int mf = 0; mf < 4; mf++)
#pragma unroll
        for (int nf = 0; nf < 4; nf++)
#pragma unroll
            for (int c = 0; c < 4; c++) acc[mf][nf][c] = 0.f;

    const int NC = D_DIM / BK;  // 32

    // prologue
    float4 regB[4];
#pragma unroll
    for (int i = 0; i < 4; i++)
        regB[i] = *(const float4*)(bW + (size_t)(kr0 + i * 8) * F_DIM);
    cp16(sA[0] + (uint32_t)(rA * (SAH * 2) + cc0 * 16), aRow + cc0 * 8);
    cp16(sA[0] + (uint32_t)(rA * (SAH * 2) + (cc0 + 1) * 16), aRow + (cc0 + 1) * 8);
    CP_COMMIT();

    for (int c = 0; c < NC; c++) {
        int buf = c & 1;
        // store B (chunk c) to smem as fp16
#pragma unroll
        for (int i = 0; i < 4; i++)
            stsB4(sB[buf] + (uint32_t)((kr0 + i * 8) * (SBH * 2) + col4 * 8), regB[i]);
        // load B (chunk c+1) into regs
        if (c + 1 < NC) {
            int kb = (c + 1) * BK;
#pragma unroll
            for (int i = 0; i < 4; i++)
                regB[i] = *(const float4*)(bW + (size_t)(kb + kr0 + i * 8) * F_DIM);
        }
        CP_WAIT(0);          // A(c) landed
        __syncthreads();     // B(c) visible; all warps done with buf^1 of previous iter
        if (c + 1 < NC) {    // prefetch A(c+1) — overlaps compute(c)
            int kb = (c + 1) * BK;
            uint32_t d0 = sA[buf ^ 1] + (uint32_t)(rA * (SAH * 2) + cc0 * 16);
            cp16(d0,      aRow + kb + cc0 * 8);
            cp16(d0 + 16, aRow + kb + (cc0 + 1) * 8);
            CP_COMMIT();
        }
        gemm_f16(sA[buf], sB[buf], wm, wn, lane, acc);
    }

    // ----- fused SiLU epilogue via smem staging of the up tile -----
    __syncthreads();
    float* s_up = (float*)smem;        // [128][68] floats = 34816 B <= 37888
    if (wn >= 64) {
#pragma unroll
        for (int mf = 0; mf < 4; mf++) {
            int r0 = wm + mf * 16 + g;
#pragma unroll
            for (int nf = 0; nf < 4; nf++) {
                int col = (wn - 64) + nf * 8 + 2 * t;
                *(float2*)&s_up[r0 * 68 + col]       = make_float2(acc[mf][nf][0], acc[mf][nf][1]);
                *(float2*)&s_up[(r0 + 8) * 68 + col] = make_float2(acc[mf][nf][2], acc[mf][nf][3]);
            }
        }
    }
    __syncthreads();
    if (wn < 64) {
#pragma unroll
        for (int mf = 0; mf < 4; mf++) {
            int r0 = wm + mf * 16 + g;
            int p0 = base + r0;
            int p1 = p0 + 8;
#pragma unroll
            for (int nf = 0; nf < 4; nf++) {
                int col = wn + nf * 8 + 2 * t;
                float2 u0 = *(float2*)&s_up[r0 * 68 + col];
                float2 u1 = *(float2*)&s_up[(r0 + 8) * 68 + col];
                if (p0 < end) {
                    float g0 = acc[mf][nf][0], g1 = acc[mf][nf][1];
                    __half2 h = __floats2half2_rn(g0 / (1.f + expf(-g0)) * u0.x,
                                                  g1 / (1.f + expf(-g1)) * u0.y);
                    *(uint32_t*)(g_h16 + (size_t)p0 * F_DIM + nb + col) = *(uint32_t*)&h;
                }
                if (p1 < end) {
                    float g2 = acc[mf][nf][2], g3 = acc[mf][nf][3];
                    __half2 h = __floats2half2_rn(g2 / (1.f + expf(-g2)) * u1.x,
                                                  g3 / (1.f + expf(-g3)) * u1.y);
                    *(uint32_t*)(g_h16 + (size_t)p1 * F_DIM + nb + col) = *(uint32_t*)&h;
                }
            }
        }
    }
}

// ---------------- 4) down GEMM: g_y[tok*2+slot] = w * (g_h16 row @ Wd[e]) ----------------
__global__ void __launch_bounds__(256, 2)
gemm_down(const float* __restrict__ Wd) {
    int e = blockIdx.z;
    int base = g_off[e] + blockIdx.x * BM;
    int end  = g_off[e + 1];
    if (base >= end) return;
    int nb = blockIdx.y * 128;
    const float* W = Wd + (size_t)e * F_DIM * D_DIM;

    extern __shared__ char smem[];
    uint32_t s0 = smem_u32(smem);
    uint32_t sA[2] = { s0, s0 + A_TILE };
    uint32_t sB[2] = { s0 + 2 * A_TILE, s0 + 2 * A_TILE + B_TILE };

    int tid = threadIdx.x, lane = tid & 31, wid = tid >> 5;
    int g = lane >> 2, t = lane & 3;
    int wm = (wid & 1) * 64, wn = (wid >> 1) * 32;

    int rA = tid >> 1;
    int cc0 = (tid & 1) * 2;
    int pA = base + rA; if (pA > end - 1) pA = end - 1;
    const __half* aRow = g_h16 + (size_t)pA * F_DIM;

    int col4 = tid & 31;
    int kr0 = tid >> 5;
    const float* bW = W + nb + col4 * 4;

    float acc[4][4][4];
#pragma unroll
    for (int mf = 0; mf < 4; mf++)
#pragma unroll
        for (int nf = 0; nf < 4; nf++)
#pragma unroll
            for (int c = 0; c < 4; c++) acc[mf][nf][c] = 0.f;

    const int NC = F_DIM / BK;  // 128

    float4 regB[4];
#pragma unroll
    for (int i = 0; i < 4; i++)
        regB[i] = *(const float4*)(bW + (size_t)(kr0 + i * 8) * D_DIM);
    cp16(sA[0] + (uint32_t)(rA * (SAH * 2) + cc0 * 16), aRow + cc0 * 8);
    cp16(sA[0] + (uint32_t)(rA * (SAH * 2) + (cc0 + 1) * 16), aRow + (cc0 + 1) * 8);
    CP_COMMIT();

    for (int c = 0; c < NC; c++) {
        int buf = c & 1;
#pragma unroll
        for (int i = 0; i < 4; i++)
            stsB4(sB[buf] + (uint32_t)((kr0 + i * 8) * (SBH * 2) + col4 * 8), regB[i]);
        if (c + 1 < NC) {
            int kb = (c + 1) * BK;
#pragma unroll
            for (int i = 0; i < 4; i++)
                regB[i] = *(const float4*)(bW + (size_t)(kb + kr0 + i * 8) * D_DIM);
        }
        CP_WAIT(0);
        __syncthreads();
        if (c + 1 < NC) {
            int kb = (c + 1) * BK;
            uint32_t d0 = sA[buf ^ 1] + (uint32_t)(rA * (SAH * 2) + cc0 * 16);
            cp16(d0,      aRow + kb + cc0 * 8);
            cp16(d0 + 16, aRow + kb + (cc0 + 1) * 8);
            CP_COMMIT();
        }
        gemm_f16(sA[buf], sB[buf], wm, wn, lane, acc);
    }

#pragma unroll
    for (int mf = 0; mf < 4; mf++) {
        int p0 = base + wm + mf * 16 + g;
        int p1 = p0 + 8;
#pragma unroll
        for (int nf = 0; nf < 4; nf++) {
            int col = nb + wn + nf * 8 + 2 * t;
            if (p0 < end) {
                float w = g_pair_w[p0];
                size_t row = (size_t)(g_pair_tok[p0] * 2 + g_pair_slot[p0]);
                *(float2*)(g_y + row * D_DIM + col) =
                    make_float2(w * acc[mf][nf][0], w * acc[mf][nf][1]);
            }
            if (p1 < end) {
                float w = g_pair_w[p1];
                size_t row = (size_t)(g_pair_tok[p1] * 2 + g_pair_slot[p1]);
                *(float2*)(g_y + row * D_DIM + col) =
                    make_float2(w * acc[mf][nf][2], w * acc[mf][nf][3]);
            }
        }
    }
}

// ---------------- 5) combine ----------------
__global__ void combine_kernel(float* __restrict__ out) {
    int i = blockIdx.x * blockDim.x + threadIdx.x;
    if (i >= T_TOK * D_DIM) return;
    int t = i >> 10;
    int d = i & (D_DIM - 1);
    out[i] = g_y[((size_t)(t * 2)) * D_DIM + d] + g_y[((size_t)(t * 2 + 1)) * D_DIM + d];
}

// ---------------- launch ----------------
extern "C" void kernel_launch(void* const* d_in, const int* in_sizes, int n_in,
                              void* d_out, int out_size) {
    const float* x  = (const float*)d_in[0];
    const float* wr = (const float*)d_in[1];
    const float* Wg = (const float*)d_in[2];
    const float* Wu = (const float*)d_in[3];
    const float* Wd = (const float*)d_in[4];
    float* out = (float*)d_out;

    cudaFuncSetAttribute(gemm_gu,   cudaFuncAttributeMaxDynamicSharedMemorySize, SMEM_TOTAL);
    cudaFuncSetAttribute(gemm_down, cudaFuncAttributeMaxDynamicSharedMemorySize, SMEM_TOTAL);

    router_kernel<<<T_TOK / 8, 256>>>(x, wr);
    cvt_x_kernel<<<(T_TOK * D_DIM / 4) / 256, 256>>>(x);
    assign_kernel<<<1, 256>>>();
    gemm_gu<<<dim3(NPAIR / BM, F_DIM / 64, E_NUM), 256, SMEM_TOTAL>>>(Wg, Wu);
    gemm_down<<<dim3(NPAIR / BM, D_DIM / 128, E_NUM), 256, SMEM_TOTAL>>>(Wd);
    combine_kernel<<<(T_TOK * D_DIM + 255) / 256, 256>>>(out);
}

// round 8
// speedup vs baseline: 1.8165x; 1.0257x over previous
#include <cuda_runtime.h>
#include <cuda_fp16.h>
#include <math.h>
#include <stdint.h>

#define T_TOK 2048
#define D_DIM 1024
#define F_DIM 4096
#define E_NUM 8
#define NPAIR (T_TOK * 2)

#define BM 128
#define BK 64
#define SAH 72     // A smem row stride (halfs) = 144B (ldmatrix conflict-free)
#define SBH 136    // B smem row stride (halfs) = 272B (ldmatrix conflict-free)
#define A_TILE (BM * SAH * 2)     // 18432 B (128 rows x 64 halfs + pad)
#define B_TILE (BK * SBH * 2)     // 17408 B (64 rows x 128 halfs + pad)
#define STAGE (A_TILE + B_TILE)   // 35840
#define NSTAGE 3
#define SMEM_TOTAL (NSTAGE * STAGE)  // 107520 -> 2 CTAs/SM

// ---------------- scratch (device globals) ----------------
__device__ int    g_off[E_NUM + 1];
__device__ int    g_pair_tok[NPAIR];
__device__ int    g_pair_slot[NPAIR];
__device__ float  g_pair_w[NPAIR];
__device__ int    g_tok_e[NPAIR];
__device__ float  g_tok_w[NPAIR];
__device__ __half g_x16[(size_t)T_TOK * D_DIM];          // 4 MB
__device__ __half g_h16[(size_t)NPAIR * F_DIM];          // 32 MB
__device__ float  g_y[(size_t)NPAIR * D_DIM];            // 16 MB
__device__ __half g_wg16[(size_t)E_NUM * D_DIM * F_DIM]; // 64 MB
__device__ __half g_wu16[(size_t)E_NUM * D_DIM * F_DIM]; // 64 MB
__device__ __half g_wd16[(size_t)E_NUM * F_DIM * D_DIM]; // 64 MB

// ---------------- PTX helpers (sm_103 baseline; no 'a'-gated features) ----------------
__device__ __forceinline__ uint32_t smem_u32(const void* p) {
    uint32_t a;
    asm("{ .reg .u64 t; cvta.to.shared.u64 t, %1; cvt.u32.u64 %0, t; }" : "=r"(a) : "l"(p));
    return a;
}
__device__ __forceinline__ void cp16(uint32_t dst, const void* src) {
    asm volatile("cp.async.cg.shared.global [%0], [%1], 16;" :: "r"(dst), "l"(src));
}
#define CP_COMMIT() asm volatile("cp.async.commit_group;" ::: "memory")
#define CP_WAIT(n)  asm volatile("cp.async.wait_group %0;" :: "n"(n) : "memory")

__device__ __forceinline__ void ldm4(uint32_t a, uint32_t* r) {
    asm volatile("ldmatrix.sync.aligned.m8n8.x4.shared.b16 {%0,%1,%2,%3}, [%4];"
        : "=r"(r[0]), "=r"(r[1]), "=r"(r[2]), "=r"(r[3]) : "r"(a));
}
__device__ __forceinline__ void ldm2t(uint32_t a, uint32_t* r) {
    asm volatile("ldmatrix.sync.aligned.m8n8.x2.trans.shared.b16 {%0,%1}, [%2];"
        : "=r"(r[0]), "=r"(r[1]) : "r"(a));
}
__device__ __forceinline__ void mma16(float* d, const uint32_t* a, const uint32_t* b) {
    asm volatile(
        "mma.sync.aligned.m16n8k16.row.col.f32.f16.f16.f32 "
        "{%0,%1,%2,%3}, {%4,%5,%6,%7}, {%8,%9}, {%0,%1,%2,%3};"
        : "+f"(d[0]), "+f"(d[1]), "+f"(d[2]), "+f"(d[3])
        : "r"(a[0]), "r"(a[1]), "r"(a[2]), "r"(a[3]), "r"(b[0]), "r"(b[1]));
}

// ---------------- 0) fp32 -> fp16 bulk convert ----------------
__global__ void cvt_kernel(const float* __restrict__ src, __half* __restrict__ dst) {
    size_t i = (size_t)blockIdx.x * 256 + threadIdx.x;   // float4 index
    float4 v = ((const float4*)src)[i];
    __half2 h0 = __floats2half2_rn(v.x, v.y);
    __half2 h1 = __floats2half2_rn(v.z, v.w);
    ((uint2*)dst)[i] = make_uint2(*(uint32_t*)&h0, *(uint32_t*)&h1);
}

// ---------------- 1) router (exact fp32) ----------------
__global__ void router_kernel(const float* __restrict__ x, const float* __restrict__ wr) {
    int warp = threadIdx.x >> 5;
    int lane = threadIdx.x & 31;
    int t = blockIdx.x * 8 + warp;
    if (t >= T_TOK) return;

    float acc[E_NUM];
#pragma unroll
    for (int e = 0; e < E_NUM; e++) acc[e] = 0.f;

    const float* xr = x + (size_t)t * D_DIM;
    for (int d = lane; d < D_DIM; d += 32) {
        float xv = xr[d];
        const float4* w4 = (const float4*)(wr + (size_t)d * E_NUM);
        float4 w0 = w4[0];
        float4 w1 = w4[1];
        acc[0] += xv * w0.x; acc[1] += xv * w0.y;
        acc[2] += xv * w0.z; acc[3] += xv * w0.w;
        acc[4] += xv * w1.x; acc[5] += xv * w1.y;
        acc[6] += xv * w1.z; acc[7] += xv * w1.w;
    }
#pragma unroll
    for (int off = 16; off > 0; off >>= 1)
#pragma unroll
        for (int e = 0; e < E_NUM; e++)
            acc[e] += __shfl_xor_sync(0xFFFFFFFFu, acc[e], off);
    if (lane == 0) {
        int i1 = 0;
#pragma unroll
        for (int e = 1; e < E_NUM; e++) if (acc[e] > acc[i1]) i1 = e;
        int i2 = (i1 == 0) ? 1 : 0;
#pragma unroll
        for (int e = 0; e < E_NUM; e++)
            if (e != i1 && acc[e] > acc[i2]) i2 = e;
        float w1 = 1.f / (1.f + expf(acc[i2] - acc[i1]));
        g_tok_e[t * 2 + 0] = i1;
        g_tok_e[t * 2 + 1] = i2;
        g_tok_w[t * 2 + 0] = w1;
        g_tok_w[t * 2 + 1] = 1.f - w1;
    }
}

// ---------------- 2) per-expert lists ----------------
__global__ void assign_kernel() {
    __shared__ int s_cnt[E_NUM];
    __shared__ int s_fill[E_NUM];
    if (threadIdx.x < E_NUM) s_cnt[threadIdx.x] = 0;
    __syncthreads();
    for (int p = threadIdx.x; p < NPAIR; p += blockDim.x)
        atomicAdd(&s_cnt[g_tok_e[p]], 1);
    __syncthreads();
    if (threadIdx.x == 0) {
        int o = 0;
        for (int e = 0; e < E_NUM; e++) { g_off[e] = o; s_fill[e] = o; o += s_cnt[e]; }
        g_off[E_NUM] = o;
    }
    __syncthreads();
    for (int p = threadIdx.x; p < NPAIR; p += blockDim.x) {
        int e = g_tok_e[p];
        int pos = atomicAdd(&s_fill[e], 1);
        g_pair_tok[pos]  = p >> 1;
        g_pair_slot[pos] = p & 1;
        g_pair_w[pos]    = g_tok_w[p];
    }
}

// ---------------- fp16 GEMM compute core, BK=64 (ldmatrix + m16n8k16) ----------------
// warp tile 64(m) x 32(n); acc[mf][nf][4]
__device__ __forceinline__ void gemm_f16(uint32_t sA, uint32_t sB,
                                         int wm, int wn, int lane,
                                         float acc[4][4][4]) {
    int r8 = lane & 7, mi = lane >> 3;
    uint32_t aAddr = sA + (uint32_t)((wm + ((mi & 1) << 3) + r8) * (SAH * 2) + ((mi >> 1) << 4));
    uint32_t bAddr = sB + (uint32_t)((lane & 15) * (SBH * 2));
#pragma unroll
    for (int ks = 0; ks < 4; ks++) {
        uint32_t Af[4][4];
#pragma unroll
        for (int mf = 0; mf < 4; mf++)
            ldm4(aAddr + (uint32_t)(mf * 16 * SAH * 2 + ks * 32), Af[mf]);
        uint32_t Bf[4][2];
#pragma unroll
        for (int nf = 0; nf < 4; nf++)
            ldm2t(bAddr + (uint32_t)(ks * 16 * SBH * 2 + (wn + nf * 8) * 2), Bf[nf]);
#pragma unroll
        for (int mf = 0; mf < 4; mf++)
#pragma unroll
            for (int nf = 0; nf < 4; nf++)
                mma16(acc[mf][nf], Af[mf], Bf[nf]);
    }
}

// ---------------- 3) fused gate+up GEMM + SiLU -> g_h16 ----------------
// CTA: 128 pairs x 64 F-cols of BOTH gate and up. B tile cols [0,64)=Wg, [64,128)=Wu.
__global__ void __launch_bounds__(256, 2)
gemm_gu() {
    int e = blockIdx.z;
    int base = g_off[e] + blockIdx.x * BM;
    int end  = g_off[e + 1];
    if (base >= end) return;
    int nb = blockIdx.y * 64;
    const __half* wg = g_wg16 + (size_t)e * D_DIM * F_DIM;
    const __half* wu = g_wu16 + (size_t)e * D_DIM * F_DIM;

    extern __shared__ char smem[];
    uint32_t s0 = smem_u32(smem);

    int tid = threadIdx.x, lane = tid & 31, wid = tid >> 5;
    int g = lane >> 2, t = lane & 3;
    int wm = (wid & 1) * 64, wn = (wid >> 1) * 32;   // wn in {0,32,64,96}

    // A gather: 4 rows per thread (rows tid>>3 + 32i), 16B each
    const __half* aTok[4];
#pragma unroll
    for (int i = 0; i < 4; i++) {
        int p = base + (tid >> 3) + i * 32;
        if (p > end - 1) p = end - 1;
        aTok[i] = g_x16 + (size_t)g_pair_tok[p] * D_DIM;
    }
    int ac16 = tid & 7;
    // B fill: 4 units per thread; unit = (row = flat>>4, cu = flat&15)
    int brow0 = tid >> 4;        // rows brow0 + 16i
    int bcu = tid & 15;
    const __half* bSrc = (bcu < 8) ? (wg + nb + bcu * 8) : (wu + nb + (bcu - 8) * 8);

    float acc[4][4][4];
#pragma unroll
    for (int mf = 0; mf < 4; mf++)
#pragma unroll
        for (int nf = 0; nf < 4; nf++)
#pragma unroll
            for (int c = 0; c < 4; c++) acc[mf][nf][c] = 0.f;

    const int NC = D_DIM / BK;  // 16

#define GU_FILL(kc, sbuf) do {                                                      \
    int _kb = (kc) * BK;                                                            \
    uint32_t _sA = (sbuf), _sB = (sbuf) + A_TILE;                                   \
    _Pragma("unroll")                                                               \
    for (int i = 0; i < 4; i++)                                                     \
        cp16(_sA + (uint32_t)(((tid >> 3) + i * 32) * (SAH * 2) + ac16 * 16),       \
             aTok[i] + _kb + ac16 * 8);                                             \
    _Pragma("unroll")                                                               \
    for (int i = 0; i < 4; i++)                                                     \
        cp16(_sB + (uint32_t)((brow0 + i * 16) * (SBH * 2) + bcu * 16),             \
             bSrc + (size_t)(_kb + brow0 + i * 16) * F_DIM);                        \
    CP_COMMIT();                                                                    \
} while (0)

    GU_FILL(0, s0);
    GU_FILL(1, s0 + STAGE);

    for (int c = 0; c < NC; c++) {
        if (c + 2 < NC) {
            CP_WAIT(1);          // group c landed
            __syncthreads();     // all warps done with compute(c-1) -> slot (c+2)%3 free
            GU_FILL(c + 2, s0 + ((c + 2) % NSTAGE) * STAGE);
        } else {
            CP_WAIT(0);
            __syncthreads();
        }
        uint32_t sS = s0 + (c % NSTAGE) * STAGE;
        gemm_f16(sS, sS + A_TILE, wm, wn, lane, acc);
    }
#undef GU_FILL

    // ----- fused SiLU epilogue via smem staging of the up tile -----
    __syncthreads();
    float* s_up = (float*)smem;        // [128][68] floats = 34816 B <= SMEM_TOTAL
    if (wn >= 64) {
#pragma unroll
        for (int mf = 0; mf < 4; mf++) {
            int r0 = wm + mf * 16 + g;
#pragma unroll
            for (int nf = 0; nf < 4; nf++) {
                int col = (wn - 64) + nf * 8 + 2 * t;
                *(float2*)&s_up[r0 * 68 + col]       = make_float2(acc[mf][nf][0], acc[mf][nf][1]);
                *(float2*)&s_up[(r0 + 8) * 68 + col] = make_float2(acc[mf][nf][2], acc[mf][nf][3]);
            }
        }
    }
    __syncthreads();
    if (wn < 64) {
#pragma unroll
        for (int mf = 0; mf < 4; mf++) {
            int r0 = wm + mf * 16 + g;
            int p0 = base + r0;
            int p1 = p0 + 8;
#pragma unroll
            for (int nf = 0; nf < 4; nf++) {
                int col = wn + nf * 8 + 2 * t;
                float2 u0 = *(float2*)&s_up[r0 * 68 + col];
                float2 u1 = *(float2*)&s_up[(r0 + 8) * 68 + col];
                if (p0 < end) {
                    float g0 = acc[mf][nf][0], g1 = acc[mf][nf][1];
                    __half2 h = __floats2half2_rn(g0 / (1.f + expf(-g0)) * u0.x,
                                                  g1 / (1.f + expf(-g1)) * u0.y);
                    *(uint32_t*)(g_h16 + (size_t)p0 * F_DIM + nb + col) = *(uint32_t*)&h;
                }
                if (p1 < end) {
                    float g2 = acc[mf][nf][2], g3 = acc[mf][nf][3];
                    __half2 h = __floats2half2_rn(g2 / (1.f + expf(-g2)) * u1.x,
                                                  g3 / (1.f + expf(-g3)) * u1.y);
                    *(uint32_t*)(g_h16 + (size_t)p1 * F_DIM + nb + col) = *(uint32_t*)&h;
                }
            }
        }
    }
}

// ---------------- 4) down GEMM: g_y[tok*2+slot] = w * (g_h16 row @ Wd16[e]) ----------------
__global__ void __launch_bounds__(256, 2)
gemm_down() {
    int e = blockIdx.z;
    int base = g_off[e] + blockIdx.x * BM;
    int end  = g_off[e + 1];
    if (base >= end) return;
    int nb = blockIdx.y * 128;
    const __half* W = g_wd16 + (size_t)e * F_DIM * D_DIM;

    extern __shared__ char smem[];
    uint32_t s0 = smem_u32(smem);

    int tid = threadIdx.x, lane = tid & 31, wid = tid >> 5;
    int g = lane >> 2, t = lane & 3;
    int wm = (wid & 1) * 64, wn = (wid >> 1) * 32;

    const __half* aRow[4];
#pragma unroll
    for (int i = 0; i < 4; i++) {
        int p = base + (tid >> 3) + i * 32;
        if (p > end - 1) p = end - 1;
        aRow[i] = g_h16 + (size_t)p * F_DIM;
    }
    int ac16 = tid & 7;
    int brow0 = tid >> 4;
    int bcu = tid & 15;
    const __half* bSrc = W + nb + bcu * 8;

    float acc[4][4][4];
#pragma unroll
    for (int mf = 0; mf < 4; mf++)
#pragma unroll
        for (int nf = 0; nf < 4; nf++)
#pragma unroll
            for (int c = 0; c < 4; c++) acc[mf][nf][c] = 0.f;

    const int NC = F_DIM / BK;  // 64

#define DN_FILL(kc, sbuf) do {                                                      \
    int _kb = (kc) * BK;                                                            \
    uint32_t _sA = (sbuf), _sB = (sbuf) + A_TILE;                                   \
    _Pragma("unroll")                                                               \
    for (int i = 0; i < 4; i++)                                                     \
        cp16(_sA + (uint32_t)(((tid >> 3) + i * 32) * (SAH * 2) + ac16 * 16),       \
             aRow[i] + _kb + ac16 * 8);                                             \
    _Pragma("unroll")                                                               \
    for (int i = 0; i < 4; i++)                                                     \
        cp16(_sB + (uint32_t)((brow0 + i * 16) * (SBH * 2) + bcu * 16),             \
             bSrc + (size_t)(_kb + brow0 + i * 16) * D_DIM);                        \
    CP_COMMIT();                                                                    \
} while (0)

    DN_FILL(0, s0);
    DN_FILL(1, s0 + STAGE);

    for (int c = 0; c < NC; c++) {
        if (c + 2 < NC) {
            CP_WAIT(1);
            __syncthreads();
            DN_FILL(c + 2, s0 + ((c + 2) % NSTAGE) * STAGE);
        } else {
            CP_WAIT(0);
            __syncthreads();
        }
        uint32_t sS = s0 + (c % NSTAGE) * STAGE;
        gemm_f16(sS, sS + A_TILE, wm, wn, lane, acc);
    }
#undef DN_FILL

#pragma unroll
    for (int mf = 0; mf < 4; mf++) {
        int p0 = base + wm + mf * 16 + g;
        int p1 = p0 + 8;
#pragma unroll
        for (int nf = 0; nf < 4; nf++) {
            int col = nb + wn + nf * 8 + 2 * t;
            if (p0 < end) {
                float w = g_pair_w[p0];
                size_t row = (size_t)(g_pair_tok[p0] * 2 + g_pair_slot[p0]);
                *(float2*)(g_y + row * D_DIM + col) =
                    make_float2(w * acc[mf][nf][0], w * acc[mf][nf][1]);
            }
            if (p1 < end) {
                float w = g_pair_w[p1];
                size_t row = (size_t)(g_pair_tok[p1] * 2 + g_pair_slot[p1]);
                *(float2*)(g_y + row * D_DIM + col) =
                    make_float2(w * acc[mf][nf][2], w * acc[mf][nf][3]);
            }
        }
    }
}

// ---------------- 5) combine ----------------
__global__ void combine_kernel(float* __restrict__ out) {
    int i = blockIdx.x * blockDim.x + threadIdx.x;
    if (i >= T_TOK * D_DIM) return;
    int t = i >> 10;
    int d = i & (D_DIM - 1);
    out[i] = g_y[((size_t)(t * 2)) * D_DIM + d] + g_y[((size_t)(t * 2 + 1)) * D_DIM + d];
}

// ---------------- launch ----------------
extern "C" void kernel_launch(void* const* d_in, const int* in_sizes, int n_in,
                              void* d_out, int out_size) {
    const float* x  = (const float*)d_in[0];
    const float* wr = (const float*)d_in[1];
    const float* Wg = (const float*)d_in[2];
    const float* Wu = (const float*)d_in[3];
    const float* Wd = (const float*)d_in[4];
    float* out = (float*)d_out;

    cudaFuncSetAttribute(gemm_gu,   cudaFuncAttributeMaxDynamicSharedMemorySize, SMEM_TOTAL);
    cudaFuncSetAttribute(gemm_down, cudaFuncAttributeMaxDynamicSharedMemorySize, SMEM_TOTAL);

    __half *wg16, *wu16, *wd16, *x16;
    cudaGetSymbolAddress((void**)&wg16, g_wg16);
    cudaGetSymbolAddress((void**)&wu16, g_wu16);
    cudaGetSymbolAddress((void**)&wd16, g_wd16);
    cudaGetSymbolAddress((void**)&x16,  g_x16);

    const int WN4 = E_NUM * D_DIM * F_DIM / 4;   // float4 count per weight tensor

    router_kernel<<<T_TOK / 8, 256>>>(x, wr);
    cvt_kernel<<<(T_TOK * D_DIM / 4) / 256, 256>>>(x, x16);
    cvt_kernel<<<WN4 / 256, 256>>>(Wg, wg16);
    cvt_kernel<<<WN4 / 256, 256>>>(Wu, wu16);
    cvt_kernel<<<WN4 / 256, 256>>>(Wd, wd16);
    assign_kernel<<<1, 256>>>();
    gemm_gu<<<dim3(NPAIR / BM, F_DIM / 64, E_NUM), 256, SMEM_TOTAL>>>();
    gemm_down<<<dim3(NPAIR / BM, D_DIM / 128, E_NUM), 256, SMEM_TOTAL>>>();
    combine_kernel<<<(T_TOK * D_DIM + 255) / 256, 256>>>(out);
}

// round 9
// speedup vs baseline: 1.8190x; 1.0014x over previous
#include <cuda_runtime.h>
#include <cuda_fp16.h>
#include <math.h>
#include <stdint.h>

#define T_TOK 2048
#define D_DIM 1024
#define F_DIM 4096
#define E_NUM 8
#define NPAIR (T_TOK * 2)

#define BM 128
#define BK 64
#define SAH 72     // A smem row stride (halfs) = 144B (ldmatrix conflict-free)
#define SBH 136    // B smem row stride (halfs) = 272B (ldmatrix conflict-free)
#define A_TILE (BM * SAH * 2)     // 18432 B (128 rows x 64 halfs + pad)
#define B_TILE (BK * SBH * 2)     // 17408 B (64 rows x 128 halfs + pad)
#define STAGE (A_TILE + B_TILE)   // 35840
#define NSTAGE 3
#define SMEM_TOTAL (NSTAGE * STAGE)  // 107520 -> 2 CTAs/SM

// ---------------- scratch (device globals) ----------------
__device__ int    g_off[E_NUM + 1];
__device__ int    g_pair_tok[NPAIR];
__device__ int    g_pair_slot[NPAIR];
__device__ float  g_pair_w[NPAIR];
__device__ int    g_tok_e[NPAIR];
__device__ float  g_tok_w[NPAIR];
__device__ __half g_x16[(size_t)T_TOK * D_DIM];          // 4 MB
__device__ __half g_h16[(size_t)NPAIR * F_DIM];          // 32 MB
__device__ float  g_y[(size_t)NPAIR * D_DIM];            // 16 MB
__device__ __half g_wg16[(size_t)E_NUM * D_DIM * F_DIM]; // 64 MB
__device__ __half g_wu16[(size_t)E_NUM * D_DIM * F_DIM]; // 64 MB
__device__ __half g_wd16[(size_t)E_NUM * F_DIM * D_DIM]; // 64 MB

// ---------------- PTX helpers (sm_103 baseline; no 'a'-gated features) ----------------
__device__ __forceinline__ uint32_t smem_u32(const void* p) {
    uint32_t a;
    asm("{ .reg .u64 t; cvta.to.shared.u64 t, %1; cvt.u32.u64 %0, t; }" : "=r"(a) : "l"(p));
    return a;
}
__device__ __forceinline__ void cp16(uint32_t dst, const void* src) {
    asm volatile("cp.async.cg.shared.global [%0], [%1], 16;" :: "r"(dst), "l"(src));
}
#define CP_COMMIT() asm volatile("cp.async.commit_group;" ::: "memory")
#define CP_WAIT(n)  asm volatile("cp.async.wait_group %0;" :: "n"(n) : "memory")

__device__ __forceinline__ void ldm4(uint32_t a, uint32_t* r) {
    asm volatile("ldmatrix.sync.aligned.m8n8.x4.shared.b16 {%0,%1,%2,%3}, [%4];"
        : "=r"(r[0]), "=r"(r[1]), "=r"(r[2]), "=r"(r[3]) : "r"(a));
}
__device__ __forceinline__ void ldm2t(uint32_t a, uint32_t* r) {
    asm volatile("ldmatrix.sync.aligned.m8n8.x2.trans.shared.b16 {%0,%1}, [%2];"
        : "=r"(r[0]), "=r"(r[1]) : "r"(a));
}
__device__ __forceinline__ void mma16(float* d, const uint32_t* a, const uint32_t* b) {
    asm volatile(
        "mma.sync.aligned.m16n8k16.row.col.f32.f16.f16.f32 "
        "{%0,%1,%2,%3}, {%4,%5,%6,%7}, {%8,%9}, {%0,%1,%2,%3};"
        : "+f"(d[0]), "+f"(d[1]), "+f"(d[2]), "+f"(d[3])
        : "r"(a[0]), "r"(a[1]), "r"(a[2]), "r"(a[3]), "r"(b[0]), "r"(b[1]));
}

// ---------------- 0) fp32 -> fp16 bulk convert ----------------
__global__ void cvt_kernel(const float* __restrict__ src, __half* __restrict__ dst) {
    size_t i = (size_t)blockIdx.x * 256 + threadIdx.x;   // float4 index
    float4 v = ((const float4*)src)[i];
    __half2 h0 = __floats2half2_rn(v.x, v.y);
    __half2 h1 = __floats2half2_rn(v.z, v.w);
    ((uint2*)dst)[i] = make_uint2(*(uint32_t*)&h0, *(uint32_t*)&h1);
}

// ---------------- 1) router (exact fp32) ----------------
__global__ void router_kernel(const float* __restrict__ x, const float* __restrict__ wr) {
    int warp = threadIdx.x >> 5;
    int lane = threadIdx.x & 31;
    int t = blockIdx.x * 8 + warp;
    if (t >= T_TOK) return;

    float acc[E_NUM];
#pragma unroll
    for (int e = 0; e < E_NUM; e++) acc[e] = 0.f;

    const float* xr = x + (size_t)t * D_DIM;
    for (int d = lane; d < D_DIM; d += 32) {
        float xv = xr[d];
        const float4* w4 = (const float4*)(wr + (size_t)d * E_NUM);
        float4 w0 = w4[0];
        float4 w1 = w4[1];
        acc[0] += xv * w0.x; acc[1] += xv * w0.y;
        acc[2] += xv * w0.z; acc[3] += xv * w0.w;
        acc[4] += xv * w1.x; acc[5] += xv * w1.y;
        acc[6] += xv * w1.z; acc[7] += xv * w1.w;
    }
#pragma unroll
    for (int off = 16; off > 0; off >>= 1)
#pragma unroll
        for (int e = 0; e < E_NUM; e++)
            acc[e] += __shfl_xor_sync(0xFFFFFFFFu, acc[e], off);
    if (lane == 0) {
        int i1 = 0;
#pragma unroll
        for (int e = 1; e < E_NUM; e++) if (acc[e] > acc[i1]) i1 = e;
        int i2 = (i1 == 0) ? 1 : 0;
#pragma unroll
        for (int e = 0; e < E_NUM; e++)
            if (e != i1 && acc[e] > acc[i2]) i2 = e;
        float w1 = 1.f / (1.f + expf(acc[i2] - acc[i1]));
        g_tok_e[t * 2 + 0] = i1;
        g_tok_e[t * 2 + 1] = i2;
        g_tok_w[t * 2 + 0] = w1;
        g_tok_w[t * 2 + 1] = 1.f - w1;
    }
}

// ---------------- 2) per-expert lists ----------------
__global__ void assign_kernel() {
    __shared__ int s_cnt[E_NUM];
    __shared__ int s_fill[E_NUM];
    if (threadIdx.x < E_NUM) s_cnt[threadIdx.x] = 0;
    __syncthreads();
    for (int p = threadIdx.x; p < NPAIR; p += blockDim.x)
        atomicAdd(&s_cnt[g_tok_e[p]], 1);
    __syncthreads();
    if (threadIdx.x == 0) {
        int o = 0;
        for (int e = 0; e < E_NUM; e++) { g_off[e] = o; s_fill[e] = o; o += s_cnt[e]; }
        g_off[E_NUM] = o;
    }
    __syncthreads();
    for (int p = threadIdx.x; p < NPAIR; p += blockDim.x) {
        int e = g_tok_e[p];
        int pos = atomicAdd(&s_fill[e], 1);
        g_pair_tok[pos]  = p >> 1;
        g_pair_slot[pos] = p & 1;
        g_pair_w[pos]    = g_tok_w[p];
    }
}

// ---------------- fp16 GEMM compute core, BK=64 (ldmatrix + m16n8k16) ----------------
// warp tile 64(m) x 32(n); acc[mf][nf][4]
__device__ __forceinline__ void gemm_f16(uint32_t sA, uint32_t sB,
                                         int wm, int wn, int lane,
                                         float acc[4][4][4]) {
    int r8 = lane & 7, mi = lane >> 3;
    uint32_t aAddr = sA + (uint32_t)((wm + ((mi & 1) << 3) + r8) * (SAH * 2) + ((mi >> 1) << 4));
    uint32_t bAddr = sB + (uint32_t)((lane & 15) * (SBH * 2));
#pragma unroll
    for (int ks = 0; ks < 4; ks++) {
        uint32_t Af[4][4];
#pragma unroll
        for (int mf = 0; mf < 4; mf++)
            ldm4(aAddr + (uint32_t)(mf * 16 * SAH * 2 + ks * 32), Af[mf]);
        uint32_t Bf[4][2];
#pragma unroll
        for (int nf = 0; nf < 4; nf++)
            ldm2t(bAddr + (uint32_t)(ks * 16 * SBH * 2 + (wn + nf * 8) * 2), Bf[nf]);
#pragma unroll
        for (int mf = 0; mf < 4; mf++)
#pragma unroll
            for (int nf = 0; nf < 4; nf++)
                mma16(acc[mf][nf], Af[mf], Bf[nf]);
    }
}

// ---------------- 3) fused gate+up GEMM + SiLU -> g_h16 ----------------
// CTA: 128 pairs x 64 F-cols of BOTH gate and up. B tile cols [0,64)=Wg, [64,128)=Wu.
__global__ void __launch_bounds__(256, 2)
gemm_gu() {
    int e = blockIdx.z;
    int base = g_off[e] + blockIdx.x * BM;
    int end  = g_off[e + 1];
    if (base >= end) return;
    int nb = blockIdx.y * 64;
    const __half* wg = g_wg16 + (size_t)e * D_DIM * F_DIM;
    const __half* wu = g_wu16 + (size_t)e * D_DIM * F_DIM;

    extern __shared__ char smem[];
    uint32_t s0 = smem_u32(smem);

    int tid = threadIdx.x, lane = tid & 31, wid = tid >> 5;
    int g = lane >> 2, t = lane & 3;
    int wm = (wid & 1) * 64, wn = (wid >> 1) * 32;   // wn in {0,32,64,96}

    // A gather: 4 rows per thread (rows tid>>3 + 32i), 16B each
    const __half* aTok[4];
#pragma unroll
    for (int i = 0; i < 4; i++) {
        int p = base + (tid >> 3) + i * 32;
        if (p > end - 1) p = end - 1;
        aTok[i] = g_x16 + (size_t)g_pair_tok[p] * D_DIM;
    }
    int ac16 = tid & 7;
    // B fill: 4 units per thread; unit = (row = flat>>4, cu = flat&15)
    int brow0 = tid >> 4;        // rows brow0 + 16i
    int bcu = tid & 15;
    const __half* bSrc = (bcu < 8) ? (wg + nb + bcu * 8) : (wu + nb + (bcu - 8) * 8);

    float acc[4][4][4];
#pragma unroll
    for (int mf = 0; mf < 4; mf++)
#pragma unroll
        for (int nf = 0; nf < 4; nf++)
#pragma unroll
            for (int c = 0; c < 4; c++) acc[mf][nf][c] = 0.f;

    const int NC = D_DIM / BK;  // 16

#define GU_FILL(kc, sbuf) do {                                                      \
    int _kb = (kc) * BK;                                                            \
    uint32_t _sA = (sbuf), _sB = (sbuf) + A_TILE;                                   \
    _Pragma("unroll")                                                               \
    for (int i = 0; i < 4; i++)                                                     \
        cp16(_sA + (uint32_t)(((tid >> 3) + i * 32) * (SAH * 2) + ac16 * 16),       \
             aTok[i] + _kb + ac16 * 8);                                             \
    _Pragma("unroll")                                                               \
    for (int i = 0; i < 4; i++)                                                     \
        cp16(_sB + (uint32_t)((brow0 + i * 16) * (SBH * 2) + bcu * 16),             \
             bSrc + (size_t)(_kb + brow0 + i * 16) * F_DIM);                        \
    CP_COMMIT();                                                                    \
} while (0)

    GU_FILL(0, s0);
    GU_FILL(1, s0 + STAGE);

    for (int c = 0; c < NC; c++) {
        if (c + 2 < NC) {
            CP_WAIT(1);          // group c landed
            __syncthreads();     // all warps done with compute(c-1) -> slot (c+2)%3 free
            GU_FILL(c + 2, s0 + ((c + 2) % NSTAGE) * STAGE);
        } else {
            CP_WAIT(0);
            __syncthreads();
        }
        uint32_t sS = s0 + (c % NSTAGE) * STAGE;
        gemm_f16(sS, sS + A_TILE, wm, wn, lane, acc);
    }
#undef GU_FILL

    // ----- fused SiLU epilogue via smem staging of the up tile -----
    __syncthreads();
    float* s_up = (float*)smem;        // [128][68] floats = 34816 B <= SMEM_TOTAL
    if (wn >= 64) {
#pragma unroll
        for (int mf = 0; mf < 4; mf++) {
            int r0 = wm + mf * 16 + g;
#pragma unroll
            for (int nf = 0; nf < 4; nf++) {
                int col = (wn - 64) + nf * 8 + 2 * t;
                *(float2*)&s_up[r0 * 68 + col]       = make_float2(acc[mf][nf][0], acc[mf][nf][1]);
                *(float2*)&s_up[(r0 + 8) * 68 + col] = make_float2(acc[mf][nf][2], acc[mf][nf][3]);
            }
        }
    }
    __syncthreads();
    if (wn < 64) {
#pragma unroll
        for (int mf = 0; mf < 4; mf++) {
            int r0 = wm + mf * 16 + g;
            int p0 = base + r0;
            int p1 = p0 + 8;
#pragma unroll
            for (int nf = 0; nf < 4; nf++) {
                int col = wn + nf * 8 + 2 * t;
                float2 u0 = *(float2*)&s_up[r0 * 68 + col];
                float2 u1 = *(float2*)&s_up[(r0 + 8) * 68 + col];
                if (p0 < end) {
                    float g0 = acc[mf][nf][0], g1 = acc[mf][nf][1];
                    __half2 h = __floats2half2_rn(g0 / (1.f + expf(-g0)) * u0.x,
                                                  g1 / (1.f + expf(-g1)) * u0.y);
                    *(uint32_t*)(g_h16 + (size_t)p0 * F_DIM + nb + col) = *(uint32_t*)&h;
                }
                if (p1 < end) {
                    float g2 = acc[mf][nf][2], g3 = acc[mf][nf][3];
                    __half2 h = __floats2half2_rn(g2 / (1.f + expf(-g2)) * u1.x,
                                                  g3 / (1.f + expf(-g3)) * u1.y);
                    *(uint32_t*)(g_h16 + (size_t)p1 * F_DIM + nb + col) = *(uint32_t*)&h;
                }
            }
        }
    }
}

// ---------------- 4) down GEMM: g_y[tok*2+slot] = w * (g_h16 row @ Wd16[e]) ----------------
__global__ void __launch_bounds__(256, 2)
gemm_down() {
    int e = blockIdx.z;
    int base = g_off[e] + blockIdx.x * BM;
    int end  = g_off[e + 1];
    if (base >= end) return;
    int nb = blockIdx.y * 128;
    const __half* W = g_wd16 + (size_t)e * F_DIM * D_DIM;

    extern __shared__ char smem[];
    uint32_t s0 = smem_u32(smem);

    int tid = threadIdx.x, lane = tid & 31, wid = tid >> 5;
    int g = lane >> 2, t = lane & 3;
    int wm = (wid & 1) * 64, wn = (wid >> 1) * 32;

    const __half* aRow[4];
#pragma unroll
    for (int i = 0; i < 4; i++) {
        int p = base + (tid >> 3) + i * 32;
        if (p > end - 1) p = end - 1;
        aRow[i] = g_h16 + (size_t)p * F_DIM;
    }
    int ac16 = tid & 7;
    int brow0 = tid >> 4;
    int bcu = tid & 15;
    const __half* bSrc = W + nb + bcu * 8;

    float acc[4][4][4];
#pragma unroll
    for (int mf = 0; mf < 4; mf++)
#pragma unroll
        for (int nf = 0; nf < 4; nf++)
#pragma unroll
            for (int c = 0; c < 4; c++) acc[mf][nf][c] = 0.f;

    const int NC = F_DIM / BK;  // 64

#define DN_FILL(kc, sbuf) do {                                                      \
    int _kb = (kc) * BK;                                                            \
    uint32_t _sA = (sbuf), _sB = (sbuf) + A_TILE;                                   \
    _Pragma("unroll")                                                               \
    for (int i = 0; i < 4; i++)                                                     \
        cp16(_sA + (uint32_t)(((tid >> 3) + i * 32) * (SAH * 2) + ac16 * 16),       \
             aRow[i] + _kb + ac16 * 8);                                             \
    _Pragma("unroll")                                                               \
    for (int i = 0; i < 4; i++)                                                     \
        cp16(_sB + (uint32_t)((brow0 + i * 16) * (SBH * 2) + bcu * 16),             \
             bSrc + (size_t)(_kb + brow0 + i * 16) * D_DIM);                        \
    CP_COMMIT();                                                                    \
} while (0)

    DN_FILL(0, s0);
    DN_FILL(1, s0 + STAGE);

    for (int c = 0; c < NC; c++) {
        if (c + 2 < NC) {
            CP_WAIT(1);
            __syncthreads();
            DN_FILL(c + 2, s0 + ((c + 2) % NSTAGE) * STAGE);
        } else {
            CP_WAIT(0);
            __syncthreads();
        }
        uint32_t sS = s0 + (c % NSTAGE) * STAGE;
        gemm_f16(sS, sS + A_TILE, wm, wn, lane, acc);
    }
#undef DN_FILL

#pragma unroll
    for (int mf = 0; mf < 4; mf++) {
        int p0 = base + wm + mf * 16 + g;
        int p1 = p0 + 8;
#pragma unroll
        for (int nf = 0; nf < 4; nf++) {
            int col = nb + wn + nf * 8 + 2 * t;
            if (p0 < end) {
                float w = g_pair_w[p0];
                size_t row = (size_t)(g_pair_tok[p0] * 2 + g_pair_slot[p0]);
                *(float2*)(g_y + row * D_DIM + col) =
                    make_float2(w * acc[mf][nf][0], w * acc[mf][nf][1]);
            }
            if (p1 < end) {
                float w = g_pair_w[p1];
                size_t row = (size_t)(g_pair_tok[p1] * 2 + g_pair_slot[p1]);
                *(float2*)(g_y + row * D_DIM + col) =
                    make_float2(w * acc[mf][nf][2], w * acc[mf][nf][3]);
            }
        }
    }
}

// ---------------- 5) combine ----------------
__global__ void combine_kernel(float* __restrict__ out) {
    int i = blockIdx.x * blockDim.x + threadIdx.x;
    if (i >= T_TOK * D_DIM) return;
    int t = i >> 10;
    int d = i & (D_DIM - 1);
    out[i] = g_y[((size_t)(t * 2)) * D_DIM + d] + g_y[((size_t)(t * 2 + 1)) * D_DIM + d];
}

// ---------------- launch ----------------
extern "C" void kernel_launch(void* const* d_in, const int* in_sizes, int n_in,
                              void* d_out, int out_size) {
    const float* x  = (const float*)d_in[0];
    const float* wr = (const float*)d_in[1];
    const float* Wg = (const float*)d_in[2];
    const float* Wu = (const float*)d_in[3];
    const float* Wd = (const float*)d_in[4];
    float* out = (float*)d_out;

    cudaFuncSetAttribute(gemm_gu,   cudaFuncAttributeMaxDynamicSharedMemorySize, SMEM_TOTAL);
    cudaFuncSetAttribute(gemm_down, cudaFuncAttributeMaxDynamicSharedMemorySize, SMEM_TOTAL);

    __half *wg16, *wu16, *wd16, *x16;
    cudaGetSymbolAddress((void**)&wg16, g_wg16);
    cudaGetSymbolAddress((void**)&wu16, g_wu16);
    cudaGetSymbolAddress((void**)&wd16, g_wd16);
    cudaGetSymbolAddress((void**)&x16,  g_x16);

    const int WN4 = E_NUM * D_DIM * F_DIM / 4;   // float4 count per weight tensor

    router_kernel<<<T_TOK / 8, 256>>>(x, wr);
    cvt_kernel<<<(T_TOK * D_DIM / 4) / 256, 256>>>(x, x16);
    cvt_kernel<<<WN4 / 256, 256>>>(Wg, wg16);
    cvt_kernel<<<WN4 / 256, 256>>>(Wu, wu16);
    cvt_kernel<<<WN4 / 256, 256>>>(Wd, wd16);
    assign_kernel<<<1, 256>>>();
    gemm_gu<<<dim3(NPAIR / BM, F_DIM / 64, E_NUM), 256, SMEM_TOTAL>>>();
    gemm_down<<<dim3(NPAIR / BM, D_DIM / 128, E_NUM), 256, SMEM_TOTAL>>>();
    combine_kernel<<<(T_TOK * D_DIM + 255) / 256, 256>>>(out);
}